// round 17
// baseline (speedup 1.0000x reference)
#include <cuda_runtime.h>
#include <cuda_fp16.h>
#include <cstdint>
#include <cstddef>

// B=1024, F=512, N=8 — HMMA fp16 (fp32 accum), all GEMMs 1-term fp16.
// 4-stage cp.async pipeline (wait_group 2 steady-state) to hide gmem latency.
// G1: h16. G2: scatters di-shifted conv operand X16. conv (persistent): Y16.
// pool (vectorized) -> p16. G3: split-K=4 + reduce. Builders fused.

#define LDK 40   // smem row stride in halves (80B, conflict-free ldmatrix)
#define NSTG 4   // pipeline stages

// ---------------- static scratch ----------------
__device__ unsigned short g_xcat16[(size_t)1024 * 1024];  // fp16 [vx|ax]
__device__ unsigned short g_W16[(size_t)4096 * 1024];     // fp16 W1
__device__ unsigned short g_h16[(size_t)8 * 1024 * 512];  // fp16 h, [z][b][f]
__device__ unsigned short g_W216[(size_t)4096 * 512];     // fp16 W2
__device__ unsigned short g_X16[(size_t)8192 * 1536];     // conv A (scatter-written;
                                                          // boundary blocks stay bss-zero)
__device__ unsigned short g_W3[(size_t)1536 * 1536];      // conv B, fp16
__device__ unsigned short g_Y16[(size_t)8192 * 1536];     // conv out, fp16
__device__ unsigned short g_p16[(size_t)1024 * 2048];     // pooled, fp16
__device__ unsigned short g_A216[(size_t)512 * 2048];     // conv2-collapsed, fp16
__device__ float g_part[(size_t)4 * 1024 * 512];          // G3 split-K partials

// ---------------- helpers ----------------
union Pack8 { unsigned short s[8]; uint4 v; };
__device__ __forceinline__ uint32_t smem_u32(const void* p) {
    uint32_t a;
    asm("{ .reg .u64 t; cvta.to.shared.u64 t, %1; cvt.u32.u64 %0, t; }" : "=r"(a) : "l"(p));
    return a;
}
__device__ __forceinline__ void ldmatrix_x4(uint32_t& r0, uint32_t& r1, uint32_t& r2, uint32_t& r3,
                                            uint32_t addr) {
    asm volatile("ldmatrix.sync.aligned.m8n8.x4.shared.b16 {%0,%1,%2,%3}, [%4];"
                 : "=r"(r0), "=r"(r1), "=r"(r2), "=r"(r3) : "r"(addr));
}
__device__ __forceinline__ void mma_16816(float* c, const uint32_t* a, const uint32_t* b) {
    asm volatile("mma.sync.aligned.m16n8k16.row.col.f32.f16.f16.f32 "
                 "{%0,%1,%2,%3}, {%4,%5,%6,%7}, {%8,%9}, {%0,%1,%2,%3};"
                 : "+f"(c[0]), "+f"(c[1]), "+f"(c[2]), "+f"(c[3])
                 : "r"(a[0]), "r"(a[1]), "r"(a[2]), "r"(a[3]), "r"(b[0]), "r"(b[1]));
}
__device__ __forceinline__ void cp_async16(uint32_t dst, const void* src) {
    asm volatile("cp.async.cg.shared.global [%0], [%1], 16;" :: "r"(dst), "l"(src));
}
#define CP_COMMIT() asm volatile("cp.async.commit_group;" ::: "memory")
#define CP_WAIT0()  asm volatile("cp.async.wait_group 0;" ::: "memory")
#define CP_WAIT1()  asm volatile("cp.async.wait_group 1;" ::: "memory")
#define CP_WAIT2()  asm volatile("cp.async.wait_group 2;" ::: "memory")

// ---------------- fused operand builders ----------------
// blocks [0,512): concat16   [512,2560): W1->fp16   [2560,3584): W2->fp16
// [3584,7680): conv2-collapse A2   [7680,8832): conv1 W3 build
__global__ void builders_kernel(const float* __restrict__ vx, const float* __restrict__ ax,
                                const float* __restrict__ W1, const float* __restrict__ W2,
                                const float* __restrict__ w2c, const float* __restrict__ c1w) {
    const int bid = blockIdx.x;
    const int tid = threadIdx.x;
    if (bid < 512) {
        int idx = bid * 256 + tid;               // 1024*128
        int kv = idx & 127, b = idx >> 7;
        const float* src = (kv < 64) ? (vx + (size_t)b * 512 + kv * 8)
                                     : (ax + (size_t)b * 512 + (kv - 64) * 8);
        float4 x0 = *(const float4*)src, x1 = *(const float4*)(src + 4);
        float vals[8] = {x0.x, x0.y, x0.z, x0.w, x1.x, x1.y, x1.z, x1.w};
        Pack8 h;
        #pragma unroll
        for (int j = 0; j < 8; j++) h.s[j] = __half_as_ushort(__float2half_rn(vals[j]));
        *(uint4*)(g_xcat16 + (size_t)b * 1024 + kv * 8) = h.v;
    } else if (bid < 3584) {
        const float* src; unsigned short* dst; int idx;
        if (bid < 2560) { src = W1; dst = g_W16;  idx = (bid - 512) * 256 + tid; }
        else            { src = W2; dst = g_W216; idx = (bid - 2560) * 256 + tid; }
        const float* s = src + (size_t)idx * 8;
        float4 x0 = *(const float4*)s, x1 = *(const float4*)(s + 4);
        float vals[8] = {x0.x, x0.y, x0.z, x0.w, x1.x, x1.y, x1.z, x1.w};
        Pack8 h;
        #pragma unroll
        for (int j = 0; j < 8; j++) h.s[j] = __half_as_ushort(__float2half_rn(vals[j]));
        *(uint4*)(dst + (size_t)idx * 8) = h.v;
    } else if (bid < 7680) {
        int idx = (bid - 3584) * 256 + tid;      // 512*512*4
        int q = idx & 3;
        int cf = idx >> 2;
        int f = cf & 511;
        int c = cf >> 9;
        int ip = q >> 1, jp = q & 1;
        const float* wb = w2c + (size_t)(c * 512 + f) * 9;
        float s = 0.f;
        #pragma unroll
        for (int i = 0; i < 2; i++)
            #pragma unroll
            for (int j = 0; j < 2; j++)
                s += wb[(ip - i + 1) * 3 + (jp - j + 1)];
        g_A216[(size_t)c * 2048 + f * 4 + q] = __half_as_ushort(__float2half_rn(0.25f * s));
    } else {
        int idx = (bid - 7680) * 256 + tid;      // 1536*3*64
        int fg = idx & 63;
        int di = (idx >> 6) % 3;
        int n  = idx / 192;
        int t = n >> 9, c = n & 511;
        Pack8 hi;
        #pragma unroll
        for (int j = 0; j < 8; j++) {
            int f = fg * 8 + j;
            size_t base = ((size_t)(c * 512 + f) * 3 + di) * 3;
            float w;
            if (t == 0)      w = c1w[base] + c1w[base + 1] + c1w[base + 2];
            else if (t == 1) w = c1w[base];
            else             w = c1w[base + 2];
            hi.s[j] = __half_as_ushort(__float2half_rn(w));
        }
        *(uint4*)(g_W3 + (size_t)n * 1536 + di * 512 + fg * 8) = hi.v;
    }
}

// ---------------- unified HMMA GEMM (4-stage cp.async pipeline) ----------------
// MODE 0: fp16 store (conv Y)       MODE 2: fp16 h store [z][b][f] (G1)
// MODE 3: X16 scatter epilogue (G2) MODE 4: raw float partial store, z-offset (G3)
// PERSIST: 1D grid of resident CTAs loops tiles; ntiles=batchA, ntx=nbP.
template <int TM, int MODE, int TERMS, bool PERSIST>
__global__ void __launch_bounds__(256, 2)
hmma_kernel(const unsigned short* __restrict__ A, const unsigned short* __restrict__ Bm,
            const float* __restrict__ bias, float* __restrict__ outF,
            unsigned short* __restrict__ outH, const float* __restrict__ vx,
            int Ks, int SKp, int nbP, int ldc,
            size_t batchA, size_t batchB, int batchBias)
{
    constexpr int THREADS = 256;
    constexpr int ROWS = TM + 128;
    constexpr int CH = ROWS * 4 / THREADS;
    constexpr int WMC = TM / 64;
    constexpr int ABUF = TM * LDK;
    constexpr int BBUF = 128 * LDK;

    extern __shared__ __align__(16) unsigned short smem[];
    unsigned short* sA = smem;                      // [NSTG][ABUF]
    unsigned short* sB = smem + NSTG * ABUF;        // [NSTG][BBUF]

    const int tid = threadIdx.x;
    const int wid = tid >> 5, lane = tid & 31;
    const int z  = blockIdx.z;
    const int wm = (wid % WMC) * 64;
    const int wn = (wid / WMC) * 32;

    const int NIT = Ks / 32;
    const int koff = (MODE == 4) ? z * NIT : 0;

    if (!PERSIST) {
        A  += (size_t)z * batchA;
        Bm += (size_t)z * batchB;
    }
    if (MODE == 2 || MODE == 3) bias += (size_t)z * batchBias;

    const uint32_t sA_base = smem_u32(sA);
    const uint32_t sB_base = smem_u32(sB);
    const int aRow = wm + (lane & 15);
    const int aKof = (lane >> 4) * 8;
    const int bRow = wn + ((lane & 7) | ((lane >> 4) << 3));
    const int bKof = ((lane >> 3) & 1) * 8;

    auto run_tile = [&](int m0, int n0) {
        // staging maps (cp.async)
        const unsigned short* gp[CH];
        uint32_t sdA[CH];
        bool isA_[CH];
        #pragma unroll
        for (int t = 0; t < CH; t++) {
            int id = tid + t * THREADS;
            int r = id >> 2, q = id & 3;
            if (r < TM) {
                gp[t] = A + (size_t)(m0 + r) * SKp + q * 8;
                sdA[t] = smem_u32(sA + r * LDK + q * 8);
                isA_[t] = true;
            } else {
                gp[t] = Bm + (size_t)(n0 + r - TM) * SKp + q * 8;
                sdA[t] = smem_u32(sB + (r - TM) * LDK + q * 8);
                isA_[t] = false;
            }
        }

        float acc[4][4][4];
        #pragma unroll
        for (int i = 0; i < 4; i++)
            #pragma unroll
            for (int j = 0; j < 4; j++)
                #pragma unroll
                for (int q = 0; q < 4; q++) acc[i][j][q] = 0.f;

        auto stage = [&](int k, int buf) {
            int kg = k + koff;
            int kA = kg;
            int kB = (TERMS == 2) ? ((kg < nbP) ? kg : kg - nbP) : kg;
            #pragma unroll
            for (int t = 0; t < CH; t++) {
                const unsigned short* src = gp[t] + (size_t)(isA_[t] ? kA : kB) * 32;
                uint32_t dst = sdA[t] + (uint32_t)buf * (isA_[t] ? ABUF : BBUF) * 2;
                cp_async16(dst, src);
            }
            CP_COMMIT();
        };

        // prime 3 stages
        stage(0, 0);
        if (NIT > 1) stage(1, 1);
        if (NIT > 2) stage(2, 2);

        int cur = 0, nxt3 = 3;
        for (int it = 0; it < NIT; it++) {
            const int rem = NIT - 1 - it;   // newer committed groups still allowed pending
            if (rem >= 2)      { CP_WAIT2(); }
            else if (rem == 1) { CP_WAIT1(); }
            else               { CP_WAIT0(); }
            __syncthreads();

            const uint32_t aBuf = sA_base + (uint32_t)cur * ABUF * 2;
            const uint32_t bBuf = sB_base + (uint32_t)cur * BBUF * 2;
            #pragma unroll
            for (int ks = 0; ks < 32; ks += 16) {
                uint32_t af[4][4], bf[4][2];
                #pragma unroll
                for (int mt = 0; mt < 4; mt++)
                    ldmatrix_x4(af[mt][0], af[mt][1], af[mt][2], af[mt][3],
                                aBuf + (uint32_t)(((aRow + mt * 16) * LDK + ks + aKof) * 2));
                #pragma unroll
                for (int np = 0; np < 2; np++)
                    ldmatrix_x4(bf[np * 2][0], bf[np * 2][1], bf[np * 2 + 1][0], bf[np * 2 + 1][1],
                                bBuf + (uint32_t)(((bRow + np * 16) * LDK + ks + bKof) * 2));
                #pragma unroll
                for (int mt = 0; mt < 4; mt++)
                    #pragma unroll
                    for (int nt = 0; nt < 4; nt++)
                        mma_16816(acc[mt][nt], af[mt], bf[nt]);
            }
            if (it + 3 < NIT) stage(it + 3, nxt3);
            cur = (cur == NSTG - 1) ? 0 : cur + 1;
            nxt3 = (nxt3 == NSTG - 1) ? 0 : nxt3 + 1;
        }
        __syncthreads();   // protect smem reuse by next persistent tile

        // epilogue
        const int erow = lane >> 2;
        const int ecol = (lane & 3) * 2;
        #pragma unroll
        for (int mt = 0; mt < 4; mt++) {
            #pragma unroll
            for (int nt = 0; nt < 4; nt++) {
                const int r0 = m0 + wm + mt * 16 + erow;
                const int c  = n0 + wn + nt * 8 + ecol;
                const float* v = acc[mt][nt];
                if (MODE == 0) {
                    #pragma unroll
                    for (int hr = 0; hr < 2; hr++) {
                        uint32_t pk = (uint32_t)__half_as_ushort(__float2half_rn(v[hr * 2]))
                                    | ((uint32_t)__half_as_ushort(__float2half_rn(v[hr * 2 + 1])) << 16);
                        *(uint32_t*)&outH[(size_t)(r0 + hr * 8) * ldc + c] = pk;
                    }
                } else if (MODE == 2) {
                    float b0 = bias[c], b1 = bias[c + 1];
                    int zz = c >> 9, f = c & 511;
                    #pragma unroll
                    for (int hr = 0; hr < 2; hr++) {
                        float y0 = fmaxf(v[hr * 2] + b0, 0.f);
                        float y1 = fmaxf(v[hr * 2 + 1] + b1, 0.f);
                        uint32_t pk = (uint32_t)__half_as_ushort(__float2half_rn(y0))
                                    | ((uint32_t)__half_as_ushort(__float2half_rn(y1)) << 16);
                        *(uint32_t*)&outH[((size_t)zz * 1024 + (r0 + hr * 8)) * 512 + f] = pk;
                    }
                } else if (MODE == 3) {
                    // G2: scatter fp16 va into X16 at the <=3 shifted positions.
                    float b0 = bias[c], b1 = bias[c + 1];
                    #pragma unroll
                    for (int hr = 0; hr < 2; hr++) {
                        int b = r0 + hr * 8;
                        float s0 = vx[(size_t)b * 512 + c];
                        float s1 = vx[(size_t)b * 512 + c + 1];
                        float y0 = s0 * fmaxf(v[hr * 2] + b0, 0.f);
                        float y1 = s1 * fmaxf(v[hr * 2 + 1] + b1, 0.f);
                        uint32_t pk = (uint32_t)__half_as_ushort(__float2half_rn(y0))
                                    | ((uint32_t)__half_as_ushort(__float2half_rn(y1)) << 16);
                        #pragma unroll
                        for (int dd = -1; dd <= 1; dd++) {
                            int i = z + dd;
                            if (i >= 0 && i <= 7) {
                                int di = 1 - dd;
                                *(uint32_t*)&outH[(size_t)(b * 8 + i) * 1536 + di * 512 + c] = pk;
                            }
                        }
                    }
                } else {  // MODE 4: raw float partial, z-offset
                    float* o = outF + (size_t)z * batchBias;
                    *(float2*)&o[(size_t)r0 * ldc + c] = make_float2(v[0], v[1]);
                    *(float2*)&o[(size_t)(r0 + 8) * ldc + c] = make_float2(v[2], v[3]);
                }
            }
        }
    };

    if (PERSIST) {
        const int ntiles = (int)batchA;
        const int ntx = nbP;
        for (int tile = blockIdx.x; tile < ntiles; tile += gridDim.x)
            run_tile((tile / ntx) * TM, (tile % ntx) * 128);
    } else {
        run_tile(blockIdx.y * TM, blockIdx.x * 128);
    }
}

// ---------------- pool: Y16 -> p16 (vectorized, 2 c per thread) ----------------
__global__ void pool16_kernel(const unsigned short* __restrict__ Y,
                              const float* __restrict__ c1b) {
    int idx = blockIdx.x * blockDim.x + threadIdx.x;   // 1024*256
    int c2 = (idx & 255) * 2, b = idx >> 8;
    float2 bias = *(const float2*)(c1b + c2);
    float m00[2] = {-1e30f, -1e30f}, m01[2] = {-1e30f, -1e30f};
    float m10[2] = {-1e30f, -1e30f}, m11[2] = {-1e30f, -1e30f};
    #pragma unroll
    for (int i = 0; i < 8; i++) {
        size_t base = (size_t)(b * 8 + i) * 1536;
        uint32_t uM = *(const uint32_t*)(Y + base + c2);
        uint32_t uB = *(const uint32_t*)(Y + base + 512 + c2);
        uint32_t uC = *(const uint32_t*)(Y + base + 1024 + c2);
        #pragma unroll
        for (int s = 0; s < 2; s++) {
            float yM = __half2float(__ushort_as_half((unsigned short)(uM >> (16 * s))));
            float yB = __half2float(__ushort_as_half((unsigned short)(uB >> (16 * s))));
            float yC = __half2float(__ushort_as_half((unsigned short)(uC >> (16 * s))));
            float vL = fmaxf(yM - yB, yM);
            float vR = fmaxf(yM - yC, yM);
            if (i < 4) { m00[s] = fmaxf(m00[s], vL); m01[s] = fmaxf(m01[s], vR); }
            else       { m10[s] = fmaxf(m10[s], vL); m11[s] = fmaxf(m11[s], vR); }
        }
    }
    Pack8 o;
    float bb[2] = {bias.x, bias.y};
    #pragma unroll
    for (int s = 0; s < 2; s++) {
        o.s[s * 4 + 0] = __half_as_ushort(__float2half_rn(m00[s] + bb[s]));
        o.s[s * 4 + 1] = __half_as_ushort(__float2half_rn(m01[s] + bb[s]));
        o.s[s * 4 + 2] = __half_as_ushort(__float2half_rn(m10[s] + bb[s]));
        o.s[s * 4 + 3] = __half_as_ushort(__float2half_rn(m11[s] + bb[s]));
    }
    *(uint4*)(g_p16 + (size_t)b * 2048 + c2 * 4) = o.v;
}

// ---------------- G3 reduce: sum 4 partials + bias, relu ----------------
__global__ void reduce_relu_kernel(const float* __restrict__ parts,
                                   const float* __restrict__ bias,
                                   float* __restrict__ out) {
    int idx = blockIdx.x * blockDim.x + threadIdx.x;   // 1024*512/4
    size_t e = (size_t)idx * 4;
    int c = (int)(e & 511);
    float4 a = *(const float4*)(parts + e);
    float4 b = *(const float4*)(parts + e + 524288);
    float4 d = *(const float4*)(parts + e + 2 * 524288);
    float4 f = *(const float4*)(parts + e + 3 * 524288);
    float4 bi = *(const float4*)(bias + c);
    float4 r;
    r.x = fmaxf(a.x + b.x + d.x + f.x + bi.x, 0.f);
    r.y = fmaxf(a.y + b.y + d.y + f.y + bi.y, 0.f);
    r.z = fmaxf(a.z + b.z + d.z + f.z + bi.z, 0.f);
    r.w = fmaxf(a.w + b.w + d.w + f.w + bi.w, 0.f);
    *(float4*)(out + e) = r;
}

// ---------------- launch ----------------
extern "C" void kernel_launch(void* const* d_in, const int* in_sizes, int n_in,
                              void* d_out, int out_size) {
    (void)in_sizes; (void)n_in; (void)out_size;
    const float* vx  = (const float*)d_in[0];
    const float* ax  = (const float*)d_in[1];
    const float* W1  = (const float*)d_in[2];
    const float* b1  = (const float*)d_in[3];
    const float* W2  = (const float*)d_in[4];
    const float* b2  = (const float*)d_in[5];
    const float* c1w = (const float*)d_in[6];
    const float* c1b = (const float*)d_in[7];
    const float* c2w = (const float*)d_in[8];
    const float* c2b = (const float*)d_in[9];
    float* out = (float*)d_out;

    void *p_xcat16, *p_W16, *p_h16, *p_W216, *p_X16, *p_W3, *p_Y16, *p_p16, *p_A216, *p_part;
    cudaGetSymbolAddress(&p_xcat16, g_xcat16);
    cudaGetSymbolAddress(&p_W16,    g_W16);
    cudaGetSymbolAddress(&p_h16,    g_h16);
    cudaGetSymbolAddress(&p_W216,   g_W216);
    cudaGetSymbolAddress(&p_X16,    g_X16);
    cudaGetSymbolAddress(&p_W3,     g_W3);
    cudaGetSymbolAddress(&p_Y16,    g_Y16);
    cudaGetSymbolAddress(&p_p16,    g_p16);
    cudaGetSymbolAddress(&p_A216,   g_A216);
    cudaGetSymbolAddress(&p_part,   g_part);

    const int SM4 = NSTG * (128 + 128) * LDK * 2;  // 81920
    cudaFuncSetAttribute((const void*)hmma_kernel<128, 2, 1, false>, cudaFuncAttributeMaxDynamicSharedMemorySize, SM4);
    cudaFuncSetAttribute((const void*)hmma_kernel<128, 3, 1, false>, cudaFuncAttributeMaxDynamicSharedMemorySize, SM4);
    cudaFuncSetAttribute((const void*)hmma_kernel<128, 0, 1, true>,  cudaFuncAttributeMaxDynamicSharedMemorySize, SM4);
    cudaFuncSetAttribute((const void*)hmma_kernel<128, 4, 1, false>, cudaFuncAttributeMaxDynamicSharedMemorySize, SM4);

    // fused operand builders
    builders_kernel<<<8832, 256>>>(vx, ax, W1, W2, c2w, c1w);

    // GEMM1 (1-term): h16 = fp16(relu(xcat16*W16^T + b1)); K=1024
    hmma_kernel<128, 2, 1, false><<<dim3(32, 8), 256, SM4>>>(
        (const unsigned short*)p_xcat16, (const unsigned short*)p_W16, b1,
        nullptr, (unsigned short*)p_h16, nullptr,
        1024, 1024, 0, 0, 0, 0, 0);

    // GEMM2 (1-term, batch z): scatter X16 = shifted fp16 va; K=512
    hmma_kernel<128, 3, 1, false><<<dim3(4, 8, 8), 256, SM4>>>(
        (const unsigned short*)p_h16, (const unsigned short*)p_W216, b2,
        nullptr, (unsigned short*)p_X16, vx,
        512, 512, 0, 0, (size_t)1024 * 512, (size_t)512 * 512, 512);

    // conv GEMM (1-term, persistent 296 CTAs): Y16 = X16*W3^T; K=1536, 768 tiles
    hmma_kernel<128, 0, 1, true><<<296, 256, SM4>>>(
        (const unsigned short*)p_X16, (const unsigned short*)p_W3, nullptr,
        nullptr, (unsigned short*)p_Y16, nullptr,
        1536, 1536, /*ntx=*/12, 1536, /*ntiles=*/768, 0, 0);

    // pool -> p16 (fp16, vectorized)
    pool16_kernel<<<1024, 256>>>((const unsigned short*)p_Y16, c1b);

    // GEMM3 (1-term, split-K=4): part_z = p16*A216^T over K-slice z; K=2048
    hmma_kernel<128, 4, 1, false><<<dim3(4, 8, 4), 256, SM4>>>(
        (const unsigned short*)p_p16, (const unsigned short*)p_A216, nullptr,
        (float*)p_part, nullptr, nullptr,
        512, 2048, 0, 512, 0, 0, 1024 * 512);

    // reduce partials + bias + relu -> out
    reduce_relu_kernel<<<512, 256>>>((const float*)p_part, c2b, out);
}